// round 9
// baseline (speedup 1.0000x reference)
#include <cuda_runtime.h>
#include <stdint.h>

#define HH 1024
#define WW 1024
#define BB 8
#define NPIX (HH*WW)          // 1048576
#define NPAIR 16              // pair = img*8 + b (img-major)
#define H1BINS 1056
#define H2BINS 4096
#define H3BINS 256
#define SROWS 16              // rows per sobel block
#define CAP 2816              // smem candidate slots per image per block

__device__ unsigned long long g_cand[NPAIR][NPIX / 8];  // (low20<<20)|idx, ~0.5MB/pair*16
__device__ unsigned int g_ccount[NPAIR];
__device__ unsigned int g_hist1[NPAIR][H1BINS];
__device__ unsigned int g_hist2[NPAIR][H2BINS];
__device__ unsigned int g_hist3[NPAIR][H3BINS];
__device__ double g_loss;
__device__ unsigned int g_sel1[NPAIR];
__device__ unsigned int g_sel2[NPAIR];
__device__ unsigned int g_krem[NPAIR];
__device__ unsigned int g_kthlow[NPAIR];

// ---------------------------------------------------------------------------
// K0: zero accumulators (graph replays must be deterministic)
// ---------------------------------------------------------------------------
__global__ void k_zero() {
    int idx = blockIdx.x * blockDim.x + threadIdx.x;
    int stride = gridDim.x * blockDim.x;
    const int n1 = NPAIR * H1BINS;
    const int n2 = NPAIR * H2BINS;
    const int n3 = NPAIR * H3BINS;
    const int tot = n1 + n2 + n3;
    unsigned int* h1 = &g_hist1[0][0];
    unsigned int* h2 = &g_hist2[0][0];
    unsigned int* h3 = &g_hist3[0][0];
    for (int i = idx; i < tot; i += stride) {
        if (i < n1) h1[i] = 0;
        else if (i < n1 + n2) h2[i - n1] = 0;
        else h3[i - n1 - n2] = 0;
    }
    if (idx < NPAIR) g_ccount[idx] = 0u;
    if (idx == 0) g_loss = 0.0;
}

// ---------------------------------------------------------------------------
// Row fetch: floats x-1..x+4 for the 4 pixels at x = 4*vx, zero at borders
// ---------------------------------------------------------------------------
__device__ __forceinline__ void load_row6(const float* __restrict__ img,
                                          int y, int vx, float* v) {
    const float* row = img + ((size_t)y << 10);
    float4 c = __ldcs((const float4*)row + vx);
    v[0] = (vx > 0) ? __ldcs(row + (vx << 2) - 1) : 0.f;
    v[1] = c.x; v[2] = c.y; v[3] = c.z; v[4] = c.w;
    v[5] = (vx < (WW / 4 - 1)) ? __ldcs(row + (vx << 2) + 4) : 0.f;
}

__device__ __forceinline__ float4 sobel_rows(const float* t, const float* m,
                                             const float* bo) {
    float g[4];
    #pragma unroll
    for (int i = 0; i < 4; i++) {
        float gx = (t[i + 2] - t[i]) + 2.f * (m[i + 2] - m[i]) + (bo[i + 2] - bo[i]);
        float gy = (t[i] - bo[i]) + 2.f * (t[i + 1] - bo[i + 1]) + (t[i + 2] - bo[i + 2]);
        g[i] = fabsf(gx) + fabsf(gy);
    }
    return make_float4(g[0], g[1], g[2], g[3]);
}

// ---------------------------------------------------------------------------
// K1: sobel(A,B,F) -> hist1 + loss ONLY (no stores). grid (64, BB), 256 thr.
// ---------------------------------------------------------------------------
__global__ void k_sobel1(const float* __restrict__ A,
                         const float* __restrict__ Bi,
                         const float* __restrict__ F) {
    __shared__ unsigned int shA[H1BINS];
    __shared__ unsigned int shB[H1BINS];
    __shared__ float wsum[8];

    const int b = blockIdx.y;
    const int tid = threadIdx.x;               // vx = float4 column
    for (int i = tid; i < H1BINS; i += 256) { shA[i] = 0u; shB[i] = 0u; }
    __syncthreads();

    const size_t plane = (size_t)b * 3 * NPIX;
    const float* pa = A + plane;
    const float* pb = Bi + plane;
    const float* pf = F + plane;

    const int y0 = blockIdx.x * SROWS;

    float ta[6], ma[6], tb[6], mb[6], tf[6], mf[6];
    if (y0 > 0) {
        load_row6(pa, y0 - 1, tid, ta);
        load_row6(pb, y0 - 1, tid, tb);
        load_row6(pf, y0 - 1, tid, tf);
    } else {
        #pragma unroll
        for (int i = 0; i < 6; i++) { ta[i] = 0.f; tb[i] = 0.f; tf[i] = 0.f; }
    }
    load_row6(pa, y0, tid, ma);
    load_row6(pb, y0, tid, mb);
    load_row6(pf, y0, tid, mf);

    float lsum = 0.f;
    #pragma unroll 2
    for (int y = y0; y < y0 + SROWS; y++) {
        float ba[6], bb[6], bf[6];
        if (y + 1 < HH) {
            load_row6(pa, y + 1, tid, ba);
            load_row6(pb, y + 1, tid, bb);
            load_row6(pf, y + 1, tid, bf);
        } else {
            #pragma unroll
            for (int i = 0; i < 6; i++) { ba[i] = 0.f; bb[i] = 0.f; bf[i] = 0.f; }
        }

        float4 ga = sobel_rows(ta, ma, ba);
        float4 gb = sobel_rows(tb, mb, bb);
        float4 gf = sobel_rows(tf, mf, bf);

        lsum += fabsf(gf.x - fmaxf(ga.x, gb.x));
        lsum += fabsf(gf.y - fmaxf(ga.y, gb.y));
        lsum += fabsf(gf.z - fmaxf(ga.z, gb.z));
        lsum += fabsf(gf.w - fmaxf(ga.w, gb.w));

        atomicAdd(&shA[min(__float_as_uint(ga.x) >> 20, (unsigned)(H1BINS - 1))], 1u);
        atomicAdd(&shA[min(__float_as_uint(ga.y) >> 20, (unsigned)(H1BINS - 1))], 1u);
        atomicAdd(&shA[min(__float_as_uint(ga.z) >> 20, (unsigned)(H1BINS - 1))], 1u);
        atomicAdd(&shA[min(__float_as_uint(ga.w) >> 20, (unsigned)(H1BINS - 1))], 1u);
        atomicAdd(&shB[min(__float_as_uint(gb.x) >> 20, (unsigned)(H1BINS - 1))], 1u);
        atomicAdd(&shB[min(__float_as_uint(gb.y) >> 20, (unsigned)(H1BINS - 1))], 1u);
        atomicAdd(&shB[min(__float_as_uint(gb.z) >> 20, (unsigned)(H1BINS - 1))], 1u);
        atomicAdd(&shB[min(__float_as_uint(gb.w) >> 20, (unsigned)(H1BINS - 1))], 1u);

        #pragma unroll
        for (int i = 0; i < 6; i++) {
            ta[i] = ma[i]; ma[i] = ba[i];
            tb[i] = mb[i]; mb[i] = bb[i];
            tf[i] = mf[i]; mf[i] = bf[i];
        }
    }

    // block-reduce loss
    float s = lsum;
    #pragma unroll
    for (int o = 16; o > 0; o >>= 1) s += __shfl_down_sync(0xffffffffu, s, o);
    if ((tid & 31) == 0) wsum[tid >> 5] = s;
    __syncthreads();
    if (tid < 8) {
        float t2 = wsum[tid];
        #pragma unroll
        for (int o = 4; o > 0; o >>= 1) t2 += __shfl_down_sync(0xffu, t2, o);
        if (tid == 0) atomicAdd(&g_loss, (double)t2);
    }

    __syncthreads();
    for (int i = tid; i < H1BINS; i += 256) {
        unsigned int ca = shA[i], cb = shB[i];
        if (ca) atomicAdd(&g_hist1[b][i], ca);
        if (cb) atomicAdd(&g_hist1[BB + b][i], cb);
    }
}

// ---------------------------------------------------------------------------
// K2: recompute sobel(A,B); write provisional mask; compact candidates.
// grid (64, BB), 256 threads.
// ---------------------------------------------------------------------------
__global__ void __launch_bounds__(256) k_sobel2(const float* __restrict__ A,
                                                const float* __restrict__ Bi,
                                                float* __restrict__ out) {
    __shared__ unsigned long long candA[CAP];
    __shared__ unsigned long long candB[CAP];
    __shared__ unsigned cntA, cntB, baseA, baseB;

    const int b = blockIdx.y;
    const int tid = threadIdx.x;
    if (tid == 0) { cntA = 0u; cntB = 0u; }
    __syncthreads();

    const unsigned selA = g_sel1[b];
    const unsigned selB = g_sel1[BB + b];
    const size_t plane = (size_t)b * 3 * NPIX;
    const float* pa = A + plane;
    const float* pb = Bi + plane;
    float* outA = out + 1 + (size_t)b * NPIX;
    float* outB = out + 1 + (size_t)(BB + b) * NPIX;

    const int y0 = blockIdx.x * SROWS;

    float ta[6], ma[6], tb[6], mb[6];
    if (y0 > 0) {
        load_row6(pa, y0 - 1, tid, ta);
        load_row6(pb, y0 - 1, tid, tb);
    } else {
        #pragma unroll
        for (int i = 0; i < 6; i++) { ta[i] = 0.f; tb[i] = 0.f; }
    }
    load_row6(pa, y0, tid, ma);
    load_row6(pb, y0, tid, mb);

    #pragma unroll 2
    for (int y = y0; y < y0 + SROWS; y++) {
        float ba[6], bb[6];
        if (y + 1 < HH) {
            load_row6(pa, y + 1, tid, ba);
            load_row6(pb, y + 1, tid, bb);
        } else {
            #pragma unroll
            for (int i = 0; i < 6; i++) { ba[i] = 0.f; bb[i] = 0.f; }
        }

        float4 ga = sobel_rows(ta, ma, ba);
        float4 gb = sobel_rows(tb, mb, bb);

        const unsigned pix = (y << 10) + (tid << 2);
        float gav[4] = {ga.x, ga.y, ga.z, ga.w};
        float gbv[4] = {gb.x, gb.y, gb.z, gb.w};
        #pragma unroll
        for (int e = 0; e < 4; e++) {
            unsigned uA = __float_as_uint(gav[e]);
            unsigned uB = __float_as_uint(gbv[e]);
            unsigned topA = uA >> 20, topB = uB >> 20;
            __stcs(outA + pix + e, (topA > selA) ? 1.0f : 0.0f);
            __stcs(outB + pix + e, (topB > selB) ? 1.0f : 0.0f);
            if (topA == selA) {
                unsigned pos = atomicAdd(&cntA, 1u);
                unsigned long long val =
                    ((unsigned long long)(uA & 0xFFFFFu) << 20)
                    | (unsigned long long)(pix + e);
                if (pos < CAP) candA[pos] = val;
                else g_cand[b][atomicAdd(&g_ccount[b], 1u)] = val;
            }
            if (topB == selB) {
                unsigned pos = atomicAdd(&cntB, 1u);
                unsigned long long val =
                    ((unsigned long long)(uB & 0xFFFFFu) << 20)
                    | (unsigned long long)(pix + e);
                if (pos < CAP) candB[pos] = val;
                else g_cand[BB + b][atomicAdd(&g_ccount[BB + b], 1u)] = val;
            }
        }

        #pragma unroll
        for (int i = 0; i < 6; i++) {
            ta[i] = ma[i]; ma[i] = ba[i];
            tb[i] = mb[i]; mb[i] = bb[i];
        }
    }

    __syncthreads();
    if (tid == 0) {
        unsigned nA = min(cntA, (unsigned)CAP);
        unsigned nB = min(cntB, (unsigned)CAP);
        baseA = nA ? atomicAdd(&g_ccount[b], nA) : 0u;
        baseB = nB ? atomicAdd(&g_ccount[BB + b], nB) : 0u;
    }
    __syncthreads();
    const unsigned nA = min(cntA, (unsigned)CAP);
    const unsigned nB = min(cntB, (unsigned)CAP);
    for (unsigned i = tid; i < nA; i += 256) g_cand[b][baseA + i] = candA[i];
    for (unsigned i = tid; i < nB; i += 256) g_cand[BB + b][baseB + i] = candB[i];
}

// ---------------------------------------------------------------------------
// Block-wide exclusive scan (blockDim multiple of 32, <=1024)
// ---------------------------------------------------------------------------
__device__ __forceinline__ unsigned block_excl_scan(unsigned local,
                                                    unsigned* warp_sh) {
    const int lane = threadIdx.x & 31;
    const int wid = threadIdx.x >> 5;
    const int nwarps = blockDim.x >> 5;
    unsigned v = local;
    #pragma unroll
    for (int o = 1; o < 32; o <<= 1) {
        unsigned n = __shfl_up_sync(0xffffffffu, v, o);
        if (lane >= o) v += n;
    }
    if (lane == 31) warp_sh[wid] = v;
    __syncthreads();
    if (wid == 0) {
        unsigned w = (lane < nwarps) ? warp_sh[lane] : 0u;
        #pragma unroll
        for (int o = 1; o < 32; o <<= 1) {
            unsigned n = __shfl_up_sync(0xffffffffu, w, o);
            if (lane >= o) w += n;
        }
        if (lane < nwarps) warp_sh[lane] = w;
    }
    __syncthreads();
    unsigned base = (wid > 0) ? warp_sh[wid - 1] : 0u;
    return base + v - local;   // exclusive prefix
}

// ---------------------------------------------------------------------------
// Parallel k-crossing scans: one block per pair, 4 contiguous bins/thread
// ---------------------------------------------------------------------------
__global__ void k_scan1(const int* __restrict__ thr) {
    __shared__ unsigned ws[32];
    const int p = blockIdx.x;
    const int tid = threadIdx.x;
    const unsigned k = (unsigned)thr[0];
    unsigned bins[4] = {0u, 0u, 0u, 0u};
    const int base = tid * 4;
    if (base < H1BINS) {
        uint4 v = *(const uint4*)&g_hist1[p][base];
        bins[0] = v.x; bins[1] = v.y; bins[2] = v.z; bins[3] = v.w;
    }
    unsigned local = bins[0] + bins[1] + bins[2] + bins[3];
    unsigned cum = block_excl_scan(local, ws);
    #pragma unroll
    for (int j = 0; j < 4; j++) {
        unsigned nb = cum + bins[j];
        if (cum < k && nb >= k) { g_sel1[p] = base + j; g_krem[p] = k - cum; }
        cum = nb;
    }
}

__global__ void k_scan2() {
    __shared__ unsigned ws[32];
    const int p = blockIdx.x;
    const int tid = threadIdx.x;
    const unsigned k = g_krem[p];
    const int base = tid * 4;
    uint4 v = *(const uint4*)&g_hist2[p][base];
    unsigned bins[4] = {v.x, v.y, v.z, v.w};
    unsigned local = bins[0] + bins[1] + bins[2] + bins[3];
    unsigned cum = block_excl_scan(local, ws);
    #pragma unroll
    for (int j = 0; j < 4; j++) {
        unsigned nb = cum + bins[j];
        if (cum < k && nb >= k) { g_sel2[p] = base + j; g_krem[p] = k - cum; }
        cum = nb;
    }
}

__global__ void k_scan3() {
    __shared__ unsigned ws[32];
    const int p = blockIdx.x;
    const int tid = threadIdx.x;
    const unsigned k = g_krem[p];
    const int base = tid * 4;
    uint4 v = *(const uint4*)&g_hist3[p][base];
    unsigned bins[4] = {v.x, v.y, v.z, v.w};
    unsigned local = bins[0] + bins[1] + bins[2] + bins[3];
    unsigned cum = block_excl_scan(local, ws);
    #pragma unroll
    for (int j = 0; j < 4; j++) {
        unsigned nb = cum + bins[j];
        if (cum < k && nb >= k)
            g_kthlow[p] = (g_sel2[p] << 8) | (unsigned)(base + j);
        cum = nb;
    }
}

// ---------------------------------------------------------------------------
// K_HIST2C: hist of bits[19:8] over compact candidates. grid (16, NPAIR)
// ---------------------------------------------------------------------------
__global__ void k_hist2c() {
    __shared__ unsigned int h[H2BINS];
    const int p = blockIdx.y;
    const int tid = threadIdx.x;
    for (int i = tid; i < H2BINS; i += 256) h[i] = 0u;
    __syncthreads();
    const unsigned cnt = g_ccount[p];
    for (unsigned i = blockIdx.x * 256 + tid; i < cnt; i += 16 * 256) {
        unsigned low = (unsigned)(g_cand[p][i] >> 20);
        atomicAdd(&h[low >> 8], 1u);
    }
    __syncthreads();
    for (int i = tid; i < H2BINS; i += 256) {
        unsigned c = h[i];
        if (c) atomicAdd(&g_hist2[p][i], c);
    }
}

// ---------------------------------------------------------------------------
// K_HIST3C: hist of bits[7:0] over candidates matching sel2. grid (16, NPAIR)
// ---------------------------------------------------------------------------
__global__ void k_hist3c() {
    __shared__ unsigned int h[H3BINS];
    const int p = blockIdx.y;
    const int tid = threadIdx.x;
    for (int i = tid; i < H3BINS; i += 256) h[i] = 0u;
    __syncthreads();
    const unsigned cnt = g_ccount[p];
    const unsigned sel2 = g_sel2[p];
    for (unsigned i = blockIdx.x * 256 + tid; i < cnt; i += 16 * 256) {
        unsigned low = (unsigned)(g_cand[p][i] >> 20);
        if ((low >> 8) == sel2) atomicAdd(&h[low & 0xFFu], 1u);
    }
    __syncthreads();
    for (int i = tid; i < H3BINS; i += 256) {
        unsigned cc = h[i];
        if (cc) atomicAdd(&g_hist3[p][i], cc);
    }
}

// ---------------------------------------------------------------------------
// K_FIX: resolve mask for candidate pixels only; write loss. grid (32, NPAIR)
// ---------------------------------------------------------------------------
__global__ void k_fix(float* __restrict__ out) {
    const int p = blockIdx.y;
    const unsigned cnt = g_ccount[p];
    const unsigned kl = g_kthlow[p];
    const size_t obase = 1 + (size_t)p * NPIX;
    for (unsigned i = blockIdx.x * 256 + threadIdx.x; i < cnt; i += 32 * 256) {
        unsigned long long c = g_cand[p][i];
        unsigned low = (unsigned)(c >> 20);
        unsigned idx = (unsigned)(c & 0xFFFFFu);
        out[obase + idx] = (low >= kl) ? 1.0f : 0.0f;
    }
    if (p == 0 && blockIdx.x == 0 && threadIdx.x == 0)
        out[0] = (float)(g_loss / 8388608.0);
}

// ---------------------------------------------------------------------------
extern "C" void kernel_launch(void* const* d_in, const int* in_sizes, int n_in,
                              void* d_out, int out_size) {
    const float* A   = (const float*)d_in[0];
    const float* Bi  = (const float*)d_in[1];
    const float* F   = (const float*)d_in[2];
    const int*   thr = (const int*)d_in[3];
    float* out = (float*)d_out;

    k_zero<<<64, 256>>>();
    k_sobel1<<<dim3(HH / SROWS, BB), 256>>>(A, Bi, F);   // (64, 8)
    k_scan1<<<NPAIR, 512>>>(thr);
    k_sobel2<<<dim3(HH / SROWS, BB), 256>>>(A, Bi, out); // (64, 8)
    k_hist2c<<<dim3(16, NPAIR), 256>>>();
    k_scan2<<<NPAIR, 1024>>>();
    k_hist3c<<<dim3(16, NPAIR), 256>>>();
    k_scan3<<<NPAIR, 64>>>();
    k_fix<<<dim3(32, NPAIR), 256>>>(out);
}

// round 10
// speedup vs baseline: 1.0846x; 1.0846x over previous
#include <cuda_runtime.h>
#include <stdint.h>

#define HH 1024
#define WW 1024
#define BB 8
#define NPIX (HH*WW)          // 1048576
#define NPAIR 16              // pair = img*8 + b (img-major)
#define H1BINS 1056
#define H2BINS 4096
#define H3BINS 256
#define SROWS 16              // rows per block in sobel1
#define SROWS2 8              // rows per block in sobel2

__device__ unsigned long long g_cand[NPAIR][NPIX / 8];  // (low20<<20)|idx
__device__ unsigned int g_ccount[NPAIR];
__device__ unsigned int g_hist1[NPAIR][H1BINS];
__device__ unsigned int g_hist2[NPAIR][H2BINS];
__device__ unsigned int g_hist3[NPAIR][H3BINS];
__device__ double g_loss;
__device__ unsigned int g_sel1[NPAIR];
__device__ unsigned int g_sel2[NPAIR];
__device__ unsigned int g_krem[NPAIR];
__device__ unsigned int g_kthlow[NPAIR];

// ---------------------------------------------------------------------------
// K0: zero accumulators (graph replays must be deterministic)
// ---------------------------------------------------------------------------
__global__ void k_zero() {
    int idx = blockIdx.x * blockDim.x + threadIdx.x;
    int stride = gridDim.x * blockDim.x;
    const int n1 = NPAIR * H1BINS;
    const int n2 = NPAIR * H2BINS;
    const int n3 = NPAIR * H3BINS;
    const int tot = n1 + n2 + n3;
    unsigned int* h1 = &g_hist1[0][0];
    unsigned int* h2 = &g_hist2[0][0];
    unsigned int* h3 = &g_hist3[0][0];
    for (int i = idx; i < tot; i += stride) {
        if (i < n1) h1[i] = 0;
        else if (i < n1 + n2) h2[i - n1] = 0;
        else h3[i - n1 - n2] = 0;
    }
    if (idx < NPAIR) g_ccount[idx] = 0u;
    if (idx == 0) g_loss = 0.0;
}

// ---------------------------------------------------------------------------
// Row fetch: floats x-1..x+4 for the 4 pixels at x = 4*vx, zero at borders
// ---------------------------------------------------------------------------
__device__ __forceinline__ void load_row6(const float* __restrict__ img,
                                          int y, int vx, float* v) {
    const float* row = img + ((size_t)y << 10);
    float4 c = __ldcs((const float4*)row + vx);
    v[0] = (vx > 0) ? __ldcs(row + (vx << 2) - 1) : 0.f;
    v[1] = c.x; v[2] = c.y; v[3] = c.z; v[4] = c.w;
    v[5] = (vx < (WW / 4 - 1)) ? __ldcs(row + (vx << 2) + 4) : 0.f;
}

__device__ __forceinline__ float4 sobel_rows(const float* t, const float* m,
                                             const float* bo) {
    float g[4];
    #pragma unroll
    for (int i = 0; i < 4; i++) {
        float gx = (t[i + 2] - t[i]) + 2.f * (m[i + 2] - m[i]) + (bo[i + 2] - bo[i]);
        float gy = (t[i] - bo[i]) + 2.f * (t[i + 1] - bo[i + 1]) + (t[i + 2] - bo[i + 2]);
        g[i] = fabsf(gx) + fabsf(gy);
    }
    return make_float4(g[0], g[1], g[2], g[3]);
}

// ---------------------------------------------------------------------------
// K1: sobel(A,B,F) -> hist1 + loss ONLY (no stores). grid (64, BB), 256 thr.
// ---------------------------------------------------------------------------
__global__ void k_sobel1(const float* __restrict__ A,
                         const float* __restrict__ Bi,
                         const float* __restrict__ F) {
    __shared__ unsigned int shA[H1BINS];
    __shared__ unsigned int shB[H1BINS];
    __shared__ float wsum[8];

    const int b = blockIdx.y;
    const int tid = threadIdx.x;               // vx = float4 column
    for (int i = tid; i < H1BINS; i += 256) { shA[i] = 0u; shB[i] = 0u; }
    __syncthreads();

    const size_t plane = (size_t)b * 3 * NPIX;
    const float* pa = A + plane;
    const float* pb = Bi + plane;
    const float* pf = F + plane;

    const int y0 = blockIdx.x * SROWS;

    float ta[6], ma[6], tb[6], mb[6], tf[6], mf[6];
    if (y0 > 0) {
        load_row6(pa, y0 - 1, tid, ta);
        load_row6(pb, y0 - 1, tid, tb);
        load_row6(pf, y0 - 1, tid, tf);
    } else {
        #pragma unroll
        for (int i = 0; i < 6; i++) { ta[i] = 0.f; tb[i] = 0.f; tf[i] = 0.f; }
    }
    load_row6(pa, y0, tid, ma);
    load_row6(pb, y0, tid, mb);
    load_row6(pf, y0, tid, mf);

    float lsum = 0.f;
    #pragma unroll 2
    for (int y = y0; y < y0 + SROWS; y++) {
        float ba[6], bb[6], bf[6];
        if (y + 1 < HH) {
            load_row6(pa, y + 1, tid, ba);
            load_row6(pb, y + 1, tid, bb);
            load_row6(pf, y + 1, tid, bf);
        } else {
            #pragma unroll
            for (int i = 0; i < 6; i++) { ba[i] = 0.f; bb[i] = 0.f; bf[i] = 0.f; }
        }

        float4 ga = sobel_rows(ta, ma, ba);
        float4 gb = sobel_rows(tb, mb, bb);
        float4 gf = sobel_rows(tf, mf, bf);

        lsum += fabsf(gf.x - fmaxf(ga.x, gb.x));
        lsum += fabsf(gf.y - fmaxf(ga.y, gb.y));
        lsum += fabsf(gf.z - fmaxf(ga.z, gb.z));
        lsum += fabsf(gf.w - fmaxf(ga.w, gb.w));

        atomicAdd(&shA[min(__float_as_uint(ga.x) >> 20, (unsigned)(H1BINS - 1))], 1u);
        atomicAdd(&shA[min(__float_as_uint(ga.y) >> 20, (unsigned)(H1BINS - 1))], 1u);
        atomicAdd(&shA[min(__float_as_uint(ga.z) >> 20, (unsigned)(H1BINS - 1))], 1u);
        atomicAdd(&shA[min(__float_as_uint(ga.w) >> 20, (unsigned)(H1BINS - 1))], 1u);
        atomicAdd(&shB[min(__float_as_uint(gb.x) >> 20, (unsigned)(H1BINS - 1))], 1u);
        atomicAdd(&shB[min(__float_as_uint(gb.y) >> 20, (unsigned)(H1BINS - 1))], 1u);
        atomicAdd(&shB[min(__float_as_uint(gb.z) >> 20, (unsigned)(H1BINS - 1))], 1u);
        atomicAdd(&shB[min(__float_as_uint(gb.w) >> 20, (unsigned)(H1BINS - 1))], 1u);

        #pragma unroll
        for (int i = 0; i < 6; i++) {
            ta[i] = ma[i]; ma[i] = ba[i];
            tb[i] = mb[i]; mb[i] = bb[i];
            tf[i] = mf[i]; mf[i] = bf[i];
        }
    }

    // block-reduce loss
    float s = lsum;
    #pragma unroll
    for (int o = 16; o > 0; o >>= 1) s += __shfl_down_sync(0xffffffffu, s, o);
    if ((tid & 31) == 0) wsum[tid >> 5] = s;
    __syncthreads();
    if (tid < 8) {
        float t2 = wsum[tid];
        #pragma unroll
        for (int o = 4; o > 0; o >>= 1) t2 += __shfl_down_sync(0xffu, t2, o);
        if (tid == 0) atomicAdd(&g_loss, (double)t2);
    }

    __syncthreads();
    for (int i = tid; i < H1BINS; i += 256) {
        unsigned int ca = shA[i], cb = shB[i];
        if (ca) atomicAdd(&g_hist1[b][i], ca);
        if (cb) atomicAdd(&g_hist1[BB + b][i], cb);
    }
}

// ---------------------------------------------------------------------------
// K2: recompute sobel(A,B); write provisional mask; compact candidates via
// per-thread local buffer + warp scan + ONE global atomic per image per block.
// grid (HH/SROWS2, BB), 256 threads.
// ---------------------------------------------------------------------------
__global__ void __launch_bounds__(256) k_sobel2(const float* __restrict__ A,
                                                const float* __restrict__ Bi,
                                                float* __restrict__ out) {
    __shared__ unsigned wtotA[8], wtotB[8];
    __shared__ unsigned baseA_s, baseB_s;

    const int b = blockIdx.y;
    const int tid = threadIdx.x;
    const int lane = tid & 31;
    const int wid = tid >> 5;

    const unsigned selA = g_sel1[b];
    const unsigned selB = g_sel1[BB + b];
    const size_t plane = (size_t)b * 3 * NPIX;
    const float* pa = A + plane;
    const float* pb = Bi + plane;
    float* outA = out + 1 + (size_t)b * NPIX;
    float* outB = out + 1 + (size_t)(BB + b) * NPIX;

    const int y0 = blockIdx.x * SROWS2;

    unsigned long long locA[4 * SROWS2];  // worst case all pixels match
    unsigned long long locB[4 * SROWS2];
    unsigned cA = 0u, cB = 0u;

    float ta[6], ma[6], tb[6], mb[6];
    if (y0 > 0) {
        load_row6(pa, y0 - 1, tid, ta);
        load_row6(pb, y0 - 1, tid, tb);
    } else {
        #pragma unroll
        for (int i = 0; i < 6; i++) { ta[i] = 0.f; tb[i] = 0.f; }
    }
    load_row6(pa, y0, tid, ma);
    load_row6(pb, y0, tid, mb);

    #pragma unroll 2
    for (int y = y0; y < y0 + SROWS2; y++) {
        float ba[6], bb[6];
        if (y + 1 < HH) {
            load_row6(pa, y + 1, tid, ba);
            load_row6(pb, y + 1, tid, bb);
        } else {
            #pragma unroll
            for (int i = 0; i < 6; i++) { ba[i] = 0.f; bb[i] = 0.f; }
        }

        float4 ga = sobel_rows(ta, ma, ba);
        float4 gb = sobel_rows(tb, mb, bb);

        const unsigned pix = (y << 10) + (tid << 2);
        float gav[4] = {ga.x, ga.y, ga.z, ga.w};
        float gbv[4] = {gb.x, gb.y, gb.z, gb.w};
        #pragma unroll
        for (int e = 0; e < 4; e++) {
            unsigned uA = __float_as_uint(gav[e]);
            unsigned uB = __float_as_uint(gbv[e]);
            unsigned topA = uA >> 20, topB = uB >> 20;
            __stcs(outA + pix + e, (topA > selA) ? 1.0f : 0.0f);
            __stcs(outB + pix + e, (topB > selB) ? 1.0f : 0.0f);
            if (topA == selA)
                locA[cA++] = ((unsigned long long)(uA & 0xFFFFFu) << 20)
                           | (unsigned long long)(pix + e);
            if (topB == selB)
                locB[cB++] = ((unsigned long long)(uB & 0xFFFFFu) << 20)
                           | (unsigned long long)(pix + e);
        }

        #pragma unroll
        for (int i = 0; i < 6; i++) {
            ta[i] = ma[i]; ma[i] = ba[i];
            tb[i] = mb[i]; mb[i] = bb[i];
        }
    }

    // warp inclusive scans of counts
    unsigned inclA = cA, inclB = cB;
    #pragma unroll
    for (int o = 1; o < 32; o <<= 1) {
        unsigned nA = __shfl_up_sync(0xffffffffu, inclA, o);
        unsigned nB = __shfl_up_sync(0xffffffffu, inclB, o);
        if (lane >= o) { inclA += nA; inclB += nB; }
    }
    if (lane == 31) { wtotA[wid] = inclA; wtotB[wid] = inclB; }
    __syncthreads();
    if (tid == 0) {
        unsigned tA = 0, tB = 0;
        #pragma unroll
        for (int w = 0; w < 8; w++) {
            unsigned xA = wtotA[w], xB = wtotB[w];
            wtotA[w] = tA; wtotB[w] = tB;
            tA += xA; tB += xB;
        }
        baseA_s = tA ? atomicAdd(&g_ccount[b], tA) : 0u;
        baseB_s = tB ? atomicAdd(&g_ccount[BB + b], tB) : 0u;
    }
    __syncthreads();

    unsigned posA = baseA_s + wtotA[wid] + (inclA - cA);
    unsigned posB = baseB_s + wtotB[wid] + (inclB - cB);
    for (unsigned i = 0; i < cA; i++) g_cand[b][posA + i] = locA[i];
    for (unsigned i = 0; i < cB; i++) g_cand[BB + b][posB + i] = locB[i];
}

// ---------------------------------------------------------------------------
// Block-wide exclusive scan (blockDim multiple of 32, <=1024)
// ---------------------------------------------------------------------------
__device__ __forceinline__ unsigned block_excl_scan(unsigned local,
                                                    unsigned* warp_sh) {
    const int lane = threadIdx.x & 31;
    const int wid = threadIdx.x >> 5;
    const int nwarps = blockDim.x >> 5;
    unsigned v = local;
    #pragma unroll
    for (int o = 1; o < 32; o <<= 1) {
        unsigned n = __shfl_up_sync(0xffffffffu, v, o);
        if (lane >= o) v += n;
    }
    if (lane == 31) warp_sh[wid] = v;
    __syncthreads();
    if (wid == 0) {
        unsigned w = (lane < nwarps) ? warp_sh[lane] : 0u;
        #pragma unroll
        for (int o = 1; o < 32; o <<= 1) {
            unsigned n = __shfl_up_sync(0xffffffffu, w, o);
            if (lane >= o) w += n;
        }
        if (lane < nwarps) warp_sh[lane] = w;
    }
    __syncthreads();
    unsigned base = (wid > 0) ? warp_sh[wid - 1] : 0u;
    return base + v - local;   // exclusive prefix
}

// ---------------------------------------------------------------------------
// Parallel k-crossing scans: one block per pair, 4 contiguous bins/thread
// ---------------------------------------------------------------------------
__global__ void k_scan1(const int* __restrict__ thr) {
    __shared__ unsigned ws[32];
    const int p = blockIdx.x;
    const int tid = threadIdx.x;
    const unsigned k = (unsigned)thr[0];
    unsigned bins[4] = {0u, 0u, 0u, 0u};
    const int base = tid * 4;
    if (base < H1BINS) {
        uint4 v = *(const uint4*)&g_hist1[p][base];
        bins[0] = v.x; bins[1] = v.y; bins[2] = v.z; bins[3] = v.w;
    }
    unsigned local = bins[0] + bins[1] + bins[2] + bins[3];
    unsigned cum = block_excl_scan(local, ws);
    #pragma unroll
    for (int j = 0; j < 4; j++) {
        unsigned nb = cum + bins[j];
        if (cum < k && nb >= k) { g_sel1[p] = base + j; g_krem[p] = k - cum; }
        cum = nb;
    }
}

__global__ void k_scan2() {
    __shared__ unsigned ws[32];
    const int p = blockIdx.x;
    const int tid = threadIdx.x;
    const unsigned k = g_krem[p];
    const int base = tid * 4;
    uint4 v = *(const uint4*)&g_hist2[p][base];
    unsigned bins[4] = {v.x, v.y, v.z, v.w};
    unsigned local = bins[0] + bins[1] + bins[2] + bins[3];
    unsigned cum = block_excl_scan(local, ws);
    #pragma unroll
    for (int j = 0; j < 4; j++) {
        unsigned nb = cum + bins[j];
        if (cum < k && nb >= k) { g_sel2[p] = base + j; g_krem[p] = k - cum; }
        cum = nb;
    }
}

__global__ void k_scan3() {
    __shared__ unsigned ws[32];
    const int p = blockIdx.x;
    const int tid = threadIdx.x;
    const unsigned k = g_krem[p];
    const int base = tid * 4;
    uint4 v = *(const uint4*)&g_hist3[p][base];
    unsigned bins[4] = {v.x, v.y, v.z, v.w};
    unsigned local = bins[0] + bins[1] + bins[2] + bins[3];
    unsigned cum = block_excl_scan(local, ws);
    #pragma unroll
    for (int j = 0; j < 4; j++) {
        unsigned nb = cum + bins[j];
        if (cum < k && nb >= k)
            g_kthlow[p] = (g_sel2[p] << 8) | (unsigned)(base + j);
        cum = nb;
    }
}

// ---------------------------------------------------------------------------
// K_HIST2C: hist of bits[19:8] over compact candidates. grid (16, NPAIR)
// ---------------------------------------------------------------------------
__global__ void k_hist2c() {
    __shared__ unsigned int h[H2BINS];
    const int p = blockIdx.y;
    const int tid = threadIdx.x;
    for (int i = tid; i < H2BINS; i += 256) h[i] = 0u;
    __syncthreads();
    const unsigned cnt = g_ccount[p];
    for (unsigned i = blockIdx.x * 256 + tid; i < cnt; i += 16 * 256) {
        unsigned low = (unsigned)(g_cand[p][i] >> 20);
        atomicAdd(&h[low >> 8], 1u);
    }
    __syncthreads();
    for (int i = tid; i < H2BINS; i += 256) {
        unsigned c = h[i];
        if (c) atomicAdd(&g_hist2[p][i], c);
    }
}

// ---------------------------------------------------------------------------
// K_HIST3C: hist of bits[7:0] over candidates matching sel2. grid (16, NPAIR)
// ---------------------------------------------------------------------------
__global__ void k_hist3c() {
    __shared__ unsigned int h[H3BINS];
    const int p = blockIdx.y;
    const int tid = threadIdx.x;
    for (int i = tid; i < H3BINS; i += 256) h[i] = 0u;
    __syncthreads();
    const unsigned cnt = g_ccount[p];
    const unsigned sel2 = g_sel2[p];
    for (unsigned i = blockIdx.x * 256 + tid; i < cnt; i += 16 * 256) {
        unsigned low = (unsigned)(g_cand[p][i] >> 20);
        if ((low >> 8) == sel2) atomicAdd(&h[low & 0xFFu], 1u);
    }
    __syncthreads();
    for (int i = tid; i < H3BINS; i += 256) {
        unsigned cc = h[i];
        if (cc) atomicAdd(&g_hist3[p][i], cc);
    }
}

// ---------------------------------------------------------------------------
// K_FIX: resolve mask for candidate pixels only; write loss. grid (32, NPAIR)
// ---------------------------------------------------------------------------
__global__ void k_fix(float* __restrict__ out) {
    const int p = blockIdx.y;
    const unsigned cnt = g_ccount[p];
    const unsigned kl = g_kthlow[p];
    const size_t obase = 1 + (size_t)p * NPIX;
    for (unsigned i = blockIdx.x * 256 + threadIdx.x; i < cnt; i += 32 * 256) {
        unsigned long long c = g_cand[p][i];
        unsigned low = (unsigned)(c >> 20);
        unsigned idx = (unsigned)(c & 0xFFFFFu);
        out[obase + idx] = (low >= kl) ? 1.0f : 0.0f;
    }
    if (p == 0 && blockIdx.x == 0 && threadIdx.x == 0)
        out[0] = (float)(g_loss / 8388608.0);
}

// ---------------------------------------------------------------------------
extern "C" void kernel_launch(void* const* d_in, const int* in_sizes, int n_in,
                              void* d_out, int out_size) {
    const float* A   = (const float*)d_in[0];
    const float* Bi  = (const float*)d_in[1];
    const float* F   = (const float*)d_in[2];
    const int*   thr = (const int*)d_in[3];
    float* out = (float*)d_out;

    k_zero<<<64, 256>>>();
    k_sobel1<<<dim3(HH / SROWS, BB), 256>>>(A, Bi, F);    // (64, 8)
    k_scan1<<<NPAIR, 512>>>(thr);
    k_sobel2<<<dim3(HH / SROWS2, BB), 256>>>(A, Bi, out); // (128, 8)
    k_hist2c<<<dim3(16, NPAIR), 256>>>();
    k_scan2<<<NPAIR, 1024>>>();
    k_hist3c<<<dim3(16, NPAIR), 256>>>();
    k_scan3<<<NPAIR, 64>>>();
    k_fix<<<dim3(32, NPAIR), 256>>>(out);
}

// round 11
// speedup vs baseline: 1.2357x; 1.1393x over previous
#include <cuda_runtime.h>
#include <stdint.h>

#define HH 1024
#define WW 1024
#define BB 8
#define NPIX (HH*WW)          // 1048576
#define NPAIR 16              // pair = img*8 + b (img-major)
#define H1BINS 1056
#define H2BINS 4096
#define H3BINS 256
#define SROWS 16              // rows per sobel block

__device__ float g_scr[2][BB][NPIX];                 // gA, gB (64 MB)
__device__ unsigned long long g_cand[NPAIR][NPIX / 4];  // (low20<<20)|idx
__device__ unsigned int g_ccount[NPAIR];
__device__ unsigned int g_hist1[NPAIR][H1BINS];
__device__ unsigned int g_hist2[NPAIR][H2BINS];
__device__ unsigned int g_hist3[NPAIR][H3BINS];
__device__ double g_loss;
__device__ unsigned int g_sel1[NPAIR];
__device__ unsigned int g_sel2[NPAIR];
__device__ unsigned int g_krem[NPAIR];
__device__ unsigned int g_kthlow[NPAIR];

// ---------------------------------------------------------------------------
// K0: zero accumulators (graph replays must be deterministic)
// ---------------------------------------------------------------------------
__global__ void k_zero() {
    int idx = blockIdx.x * blockDim.x + threadIdx.x;
    int stride = gridDim.x * blockDim.x;
    const int n1 = NPAIR * H1BINS;
    const int n2 = NPAIR * H2BINS;
    const int n3 = NPAIR * H3BINS;
    const int tot = n1 + n2 + n3;
    unsigned int* h1 = &g_hist1[0][0];
    unsigned int* h2 = &g_hist2[0][0];
    unsigned int* h3 = &g_hist3[0][0];
    for (int i = idx; i < tot; i += stride) {
        if (i < n1) h1[i] = 0;
        else if (i < n1 + n2) h2[i - n1] = 0;
        else h3[i - n1 - n2] = 0;
    }
    if (idx < NPAIR) g_ccount[idx] = 0u;
    if (idx == 0) g_loss = 0.0;
}

// ---------------------------------------------------------------------------
// Row fetch: floats x-1..x+4 for the 4 pixels at x = 4*vx, zero at borders
// ---------------------------------------------------------------------------
__device__ __forceinline__ void load_row6(const float* __restrict__ img,
                                          int y, int vx, float* v) {
    const float* row = img + ((size_t)y << 10);
    float4 c = __ldcs((const float4*)row + vx);
    v[0] = (vx > 0) ? __ldcs(row + (vx << 2) - 1) : 0.f;
    v[1] = c.x; v[2] = c.y; v[3] = c.z; v[4] = c.w;
    v[5] = (vx < (WW / 4 - 1)) ? __ldcs(row + (vx << 2) + 4) : 0.f;
}

__device__ __forceinline__ float4 sobel_rows(const float* t, const float* m,
                                             const float* bo) {
    float g[4];
    #pragma unroll
    for (int i = 0; i < 4; i++) {
        float gx = (t[i + 2] - t[i]) + 2.f * (m[i + 2] - m[i]) + (bo[i + 2] - bo[i]);
        float gy = (t[i] - bo[i]) + 2.f * (t[i + 1] - bo[i + 1]) + (t[i + 2] - bo[i + 2]);
        g[i] = fabsf(gx) + fabsf(gy);
    }
    return make_float4(g[0], g[1], g[2], g[3]);
}

// ---------------------------------------------------------------------------
// K1: fused sobel(A,B,F) + scratch store + loss + hist1. grid (64, BB).
// ---------------------------------------------------------------------------
__global__ void k_sobel(const float* __restrict__ A,
                        const float* __restrict__ Bi,
                        const float* __restrict__ F) {
    __shared__ unsigned int shA[H1BINS];
    __shared__ unsigned int shB[H1BINS];
    __shared__ float wsum[8];

    const int b = blockIdx.y;
    const int tid = threadIdx.x;               // vx = float4 column
    for (int i = tid; i < H1BINS; i += 256) { shA[i] = 0u; shB[i] = 0u; }
    __syncthreads();

    const size_t plane = (size_t)b * 3 * NPIX;
    const float* pa = A + plane;
    const float* pb = Bi + plane;
    const float* pf = F + plane;
    float4* outA = (float4*)g_scr[0][b];
    float4* outB = (float4*)g_scr[1][b];

    const int y0 = blockIdx.x * SROWS;

    float ta[6], ma[6], tb[6], mb[6], tf[6], mf[6];
    if (y0 > 0) {
        load_row6(pa, y0 - 1, tid, ta);
        load_row6(pb, y0 - 1, tid, tb);
        load_row6(pf, y0 - 1, tid, tf);
    } else {
        #pragma unroll
        for (int i = 0; i < 6; i++) { ta[i] = 0.f; tb[i] = 0.f; tf[i] = 0.f; }
    }
    load_row6(pa, y0, tid, ma);
    load_row6(pb, y0, tid, mb);
    load_row6(pf, y0, tid, mf);

    float lsum = 0.f;
    #pragma unroll 2
    for (int y = y0; y < y0 + SROWS; y++) {
        float ba[6], bb[6], bf[6];
        if (y + 1 < HH) {
            load_row6(pa, y + 1, tid, ba);
            load_row6(pb, y + 1, tid, bb);
            load_row6(pf, y + 1, tid, bf);
        } else {
            #pragma unroll
            for (int i = 0; i < 6; i++) { ba[i] = 0.f; bb[i] = 0.f; bf[i] = 0.f; }
        }

        float4 ga = sobel_rows(ta, ma, ba);
        float4 gb = sobel_rows(tb, mb, bb);
        float4 gf = sobel_rows(tf, mf, bf);

        const int vec = (y << 8) + tid;
        outA[vec] = ga;
        outB[vec] = gb;

        lsum += fabsf(gf.x - fmaxf(ga.x, gb.x));
        lsum += fabsf(gf.y - fmaxf(ga.y, gb.y));
        lsum += fabsf(gf.z - fmaxf(ga.z, gb.z));
        lsum += fabsf(gf.w - fmaxf(ga.w, gb.w));

        atomicAdd(&shA[min(__float_as_uint(ga.x) >> 20, (unsigned)(H1BINS - 1))], 1u);
        atomicAdd(&shA[min(__float_as_uint(ga.y) >> 20, (unsigned)(H1BINS - 1))], 1u);
        atomicAdd(&shA[min(__float_as_uint(ga.z) >> 20, (unsigned)(H1BINS - 1))], 1u);
        atomicAdd(&shA[min(__float_as_uint(ga.w) >> 20, (unsigned)(H1BINS - 1))], 1u);
        atomicAdd(&shB[min(__float_as_uint(gb.x) >> 20, (unsigned)(H1BINS - 1))], 1u);
        atomicAdd(&shB[min(__float_as_uint(gb.y) >> 20, (unsigned)(H1BINS - 1))], 1u);
        atomicAdd(&shB[min(__float_as_uint(gb.z) >> 20, (unsigned)(H1BINS - 1))], 1u);
        atomicAdd(&shB[min(__float_as_uint(gb.w) >> 20, (unsigned)(H1BINS - 1))], 1u);

        #pragma unroll
        for (int i = 0; i < 6; i++) {
            ta[i] = ma[i]; ma[i] = ba[i];
            tb[i] = mb[i]; mb[i] = bb[i];
            tf[i] = mf[i]; mf[i] = bf[i];
        }
    }

    // block-reduce loss
    float s = lsum;
    #pragma unroll
    for (int o = 16; o > 0; o >>= 1) s += __shfl_down_sync(0xffffffffu, s, o);
    if ((tid & 31) == 0) wsum[tid >> 5] = s;
    __syncthreads();
    if (tid < 8) {
        float t2 = wsum[tid];
        #pragma unroll
        for (int o = 4; o > 0; o >>= 1) t2 += __shfl_down_sync(0xffu, t2, o);
        if (tid == 0) atomicAdd(&g_loss, (double)t2);
    }

    __syncthreads();
    for (int i = tid; i < H1BINS; i += 256) {
        unsigned int ca = shA[i], cb = shB[i];
        if (ca) atomicAdd(&g_hist1[b][i], ca);
        if (cb) atomicAdd(&g_hist1[BB + b][i], cb);
    }
}

// ---------------------------------------------------------------------------
// K_PASS2: one streaming pass over scratch. Per thread: 1 uint4.
//   - provisional mask staged in smem -> aligned float4 stores
//   - candidates: block-aggregated compaction (1 global atomic per block)
// grid (1024, NPAIR), 256 threads.
// ---------------------------------------------------------------------------
__global__ void __launch_bounds__(256) k_pass2(float* __restrict__ out) {
    __shared__ float stage[1024];
    __shared__ unsigned wtot[8];
    __shared__ unsigned blockbase;

    const int p = blockIdx.y;
    const int tid = threadIdx.x;
    const int lane = tid & 31;
    const int wid = tid >> 5;
    const unsigned sel = g_sel1[p];

    const uint4* __restrict__ src =
        (const uint4*)&g_scr[0][0][0] + (size_t)p * (NPIX / 4);
    const unsigned v = blockIdx.x * 256 + tid;
    uint4 d = src[v];
    unsigned uu[4] = {d.x, d.y, d.z, d.w};

    float m[4];
    unsigned cnt = 0;
    #pragma unroll
    for (int e = 0; e < 4; e++) {
        unsigned top = uu[e] >> 20;
        m[e] = (top > sel) ? 1.0f : 0.0f;
        cnt += (top == sel);
    }
    *(float4*)&stage[tid << 2] = make_float4(m[0], m[1], m[2], m[3]);

    // warp inclusive scan of counts
    unsigned incl = cnt;
    #pragma unroll
    for (int o = 1; o < 32; o <<= 1) {
        unsigned n = __shfl_up_sync(0xffffffffu, incl, o);
        if (lane >= o) incl += n;
    }
    if (lane == 31) wtot[wid] = incl;
    __syncthreads();                 // covers stage[] and wtot[]
    if (tid == 0) {
        unsigned t = 0;
        #pragma unroll
        for (int w = 0; w < 8; w++) { unsigned x = wtot[w]; wtot[w] = t; t += x; }
        blockbase = t ? atomicAdd(&g_ccount[p], t) : 0u;
    }
    __syncthreads();

    // write candidates at known offsets (registers still live)
    if (cnt) {
        unsigned pos = blockbase + wtot[wid] + (incl - cnt);
        const unsigned pixbase = v << 2;
        #pragma unroll
        for (int e = 0; e < 4; e++) {
            unsigned u = uu[e];
            if ((u >> 20) == sel) {
                g_cand[p][pos++] =
                    ((unsigned long long)(u & 0xFFFFFu) << 20)
                    | (unsigned long long)(pixbase + e);
            }
        }
    }

    // mask stores: out+1 misalignment -> aligned float4 at stage idx 3 mod 4
    const size_t obase = 1 + (size_t)p * NPIX + ((size_t)blockIdx.x << 10);
    if (tid < 255) {
        float4 w = make_float4(stage[(tid << 2) + 3], stage[(tid << 2) + 4],
                               stage[(tid << 2) + 5], stage[(tid << 2) + 6]);
        __stcs((float4*)(out + obase + (tid << 2) + 3), w);
    }
    if (tid >= 252 && tid < 255) out[obase + (tid - 252)] = stage[tid - 252];
    if (tid == 255) out[obase + 1023] = stage[1023];
}

// ---------------------------------------------------------------------------
// Block-wide exclusive scan (blockDim multiple of 32, <=1024)
// ---------------------------------------------------------------------------
__device__ __forceinline__ unsigned block_excl_scan(unsigned local,
                                                    unsigned* warp_sh) {
    const int lane = threadIdx.x & 31;
    const int wid = threadIdx.x >> 5;
    const int nwarps = blockDim.x >> 5;
    unsigned v = local;
    #pragma unroll
    for (int o = 1; o < 32; o <<= 1) {
        unsigned n = __shfl_up_sync(0xffffffffu, v, o);
        if (lane >= o) v += n;
    }
    if (lane == 31) warp_sh[wid] = v;
    __syncthreads();
    if (wid == 0) {
        unsigned w = (lane < nwarps) ? warp_sh[lane] : 0u;
        #pragma unroll
        for (int o = 1; o < 32; o <<= 1) {
            unsigned n = __shfl_up_sync(0xffffffffu, w, o);
            if (lane >= o) w += n;
        }
        if (lane < nwarps) warp_sh[lane] = w;
    }
    __syncthreads();
    unsigned base = (wid > 0) ? warp_sh[wid - 1] : 0u;
    return base + v - local;   // exclusive prefix
}

// ---------------------------------------------------------------------------
// Parallel k-crossing scans: one block per pair, 4 contiguous bins/thread
// ---------------------------------------------------------------------------
__global__ void k_scan1(const int* __restrict__ thr) {
    __shared__ unsigned ws[32];
    const int p = blockIdx.x;
    const int tid = threadIdx.x;
    const unsigned k = (unsigned)thr[0];
    unsigned bins[4] = {0u, 0u, 0u, 0u};
    const int base = tid * 4;
    if (base < H1BINS) {
        uint4 v = *(const uint4*)&g_hist1[p][base];
        bins[0] = v.x; bins[1] = v.y; bins[2] = v.z; bins[3] = v.w;
    }
    unsigned local = bins[0] + bins[1] + bins[2] + bins[3];
    unsigned cum = block_excl_scan(local, ws);
    #pragma unroll
    for (int j = 0; j < 4; j++) {
        unsigned nb = cum + bins[j];
        if (cum < k && nb >= k) { g_sel1[p] = base + j; g_krem[p] = k - cum; }
        cum = nb;
    }
}

__global__ void k_scan2() {
    __shared__ unsigned ws[32];
    const int p = blockIdx.x;
    const int tid = threadIdx.x;
    const unsigned k = g_krem[p];
    const int base = tid * 4;
    uint4 v = *(const uint4*)&g_hist2[p][base];
    unsigned bins[4] = {v.x, v.y, v.z, v.w};
    unsigned local = bins[0] + bins[1] + bins[2] + bins[3];
    unsigned cum = block_excl_scan(local, ws);
    #pragma unroll
    for (int j = 0; j < 4; j++) {
        unsigned nb = cum + bins[j];
        if (cum < k && nb >= k) { g_sel2[p] = base + j; g_krem[p] = k - cum; }
        cum = nb;
    }
}

__global__ void k_scan3() {
    __shared__ unsigned ws[32];
    const int p = blockIdx.x;
    const int tid = threadIdx.x;
    const unsigned k = g_krem[p];
    const int base = tid * 4;
    uint4 v = *(const uint4*)&g_hist3[p][base];
    unsigned bins[4] = {v.x, v.y, v.z, v.w};
    unsigned local = bins[0] + bins[1] + bins[2] + bins[3];
    unsigned cum = block_excl_scan(local, ws);
    #pragma unroll
    for (int j = 0; j < 4; j++) {
        unsigned nb = cum + bins[j];
        if (cum < k && nb >= k)
            g_kthlow[p] = (g_sel2[p] << 8) | (unsigned)(base + j);
        cum = nb;
    }
}

// ---------------------------------------------------------------------------
// K_HIST2C: hist of bits[19:8] over compact candidates. grid (16, NPAIR)
// ---------------------------------------------------------------------------
__global__ void k_hist2c() {
    __shared__ unsigned int h[H2BINS];
    const int p = blockIdx.y;
    const int tid = threadIdx.x;
    for (int i = tid; i < H2BINS; i += 256) h[i] = 0u;
    __syncthreads();
    const unsigned cnt = g_ccount[p];
    for (unsigned i = blockIdx.x * 256 + tid; i < cnt; i += 16 * 256) {
        unsigned low = (unsigned)(g_cand[p][i] >> 20);
        atomicAdd(&h[low >> 8], 1u);
    }
    __syncthreads();
    for (int i = tid; i < H2BINS; i += 256) {
        unsigned c = h[i];
        if (c) atomicAdd(&g_hist2[p][i], c);
    }
}

// ---------------------------------------------------------------------------
// K_HIST3C: hist of bits[7:0] over candidates matching sel2. grid (16, NPAIR)
// ---------------------------------------------------------------------------
__global__ void k_hist3c() {
    __shared__ unsigned int h[H3BINS];
    const int p = blockIdx.y;
    const int tid = threadIdx.x;
    for (int i = tid; i < H3BINS; i += 256) h[i] = 0u;
    __syncthreads();
    const unsigned cnt = g_ccount[p];
    const unsigned sel2 = g_sel2[p];
    for (unsigned i = blockIdx.x * 256 + tid; i < cnt; i += 16 * 256) {
        unsigned low = (unsigned)(g_cand[p][i] >> 20);
        if ((low >> 8) == sel2) atomicAdd(&h[low & 0xFFu], 1u);
    }
    __syncthreads();
    for (int i = tid; i < H3BINS; i += 256) {
        unsigned cc = h[i];
        if (cc) atomicAdd(&g_hist3[p][i], cc);
    }
}

// ---------------------------------------------------------------------------
// K_FIX: resolve mask for candidate pixels only; write loss. grid (32, NPAIR)
// ---------------------------------------------------------------------------
__global__ void k_fix(float* __restrict__ out) {
    const int p = blockIdx.y;
    const unsigned cnt = g_ccount[p];
    const unsigned kl = g_kthlow[p];
    const size_t obase = 1 + (size_t)p * NPIX;
    for (unsigned i = blockIdx.x * 256 + threadIdx.x; i < cnt; i += 32 * 256) {
        unsigned long long c = g_cand[p][i];
        unsigned low = (unsigned)(c >> 20);
        unsigned idx = (unsigned)(c & 0xFFFFFu);
        out[obase + idx] = (low >= kl) ? 1.0f : 0.0f;
    }
    if (p == 0 && blockIdx.x == 0 && threadIdx.x == 0)
        out[0] = (float)(g_loss / 8388608.0);
}

// ---------------------------------------------------------------------------
extern "C" void kernel_launch(void* const* d_in, const int* in_sizes, int n_in,
                              void* d_out, int out_size) {
    const float* A   = (const float*)d_in[0];
    const float* Bi  = (const float*)d_in[1];
    const float* F   = (const float*)d_in[2];
    const int*   thr = (const int*)d_in[3];
    float* out = (float*)d_out;

    k_zero<<<64, 256>>>();
    k_sobel<<<dim3(HH / SROWS, BB), 256>>>(A, Bi, F);    // (64, 8)
    k_scan1<<<NPAIR, 512>>>(thr);
    k_pass2<<<dim3(NPIX / 4 / 256, NPAIR), 256>>>(out);  // (1024, 16)
    k_hist2c<<<dim3(16, NPAIR), 256>>>();
    k_scan2<<<NPAIR, 1024>>>();
    k_hist3c<<<dim3(16, NPAIR), 256>>>();
    k_scan3<<<NPAIR, 64>>>();
    k_fix<<<dim3(32, NPAIR), 256>>>(out);
}